// round 10
// baseline (speedup 1.0000x reference)
#include <cuda_runtime.h>
#include <cuda_bf16.h>
#include <cstdint>

// Problem constants (fixed by the reference)
#define B_SEG   16
#define D_F     128            // fine feature dim  (32 float4, 512 B/row)
#define D_C     256            // coarse feature dim (64 float4, 1024 B/row)
#define D_OUT   (D_C + D_F)    // 384

// 64 KB tiles, 128-thread CTAs, occupancy 16 (2368 resident slots on 148 SMs).
// fine: 524288/128 = 4096 tiles ; coarse: 32768/64 = 512 tiles ; total 4608
// => ~1.95 waves; wave>=2 CTAs are placed by the HW work-stealer, giving
// dynamic tail balancing with zero software overhead.
#define TILE_F  128            // fine rows per tile
#define TILE_C  64             // coarse rows per tile
#define NT_C    512            // coarse tiles (first in grid)

// Self-restoring device state (zero at module load; finalize resets it).
__device__ float        g_scratch[B_SEG * D_OUT];
__device__ unsigned int g_count = 0u;

// ---------------------------------------------------------------------------
// Static small-tile segment-sum + last-block finalize (single kernel).
// blockIdx.x < NT_C -> coarse tile, else fine tile.
// 128 threads: fine -> 32 float4 cols x 4 row lanes; coarse -> 64 x 2.
// ---------------------------------------------------------------------------
__global__ __launch_bounds__(128, 16)
void pare_mw_kernel(const float4* __restrict__ feats_c,
                    const float4* __restrict__ feats_f,
                    const int* __restrict__ lengths_c,
                    const int* __restrict__ lengths_f,
                    float* __restrict__ out,
                    int n_c, int n_f) {
    __shared__ float4 shred[128];
    __shared__ int    scum[B_SEG + 1];
    __shared__ bool   sdone;
    const int tid = threadIdx.x;

    const bool is_c = (blockIdx.x < (unsigned)NT_C);

    if (tid == 0) {
        const int* L = is_c ? lengths_c : lengths_f;
        int acc = 0;
        scum[0] = 0;
#pragma unroll
        for (int i = 0; i < B_SEG; ++i) { acc += L[i]; scum[i + 1] = acc; }
    }
    __syncthreads();

    if (is_c) {
        // ------------- coarse: 64 float4 cols, 2 row lanes -------------
        const int c  = tid & 63;
        const int rr = tid >> 6;

        int r0 = blockIdx.x * TILE_C;
        int r1 = r0 + TILE_C; if (r1 > n_c) r1 = n_c;

        int s = 0;
        while (scum[s + 1] <= r0) ++s;

        while (r0 < r1) {
            int e = scum[s + 1]; if (e > r1) e = r1;

            float4 acc = make_float4(0.f, 0.f, 0.f, 0.f);
            const float4* base = feats_c + c;
#pragma unroll 4
            for (int r = r0 + rr; r < e; r += 2) {
                float4 v = __ldcs(base + (size_t)r * 64);
                acc.x += v.x; acc.y += v.y; acc.z += v.z; acc.w += v.w;
            }

            shred[tid] = acc;
            __syncthreads();
            if (rr == 0) {
                float4 v1 = shred[64 + c];
                float4 t  = shred[c];
                t.x += v1.x; t.y += v1.y; t.z += v1.z; t.w += v1.w;
                float* o = g_scratch + s * D_OUT + c * 4;
                atomicAdd(o + 0, t.x);
                atomicAdd(o + 1, t.y);
                atomicAdd(o + 2, t.z);
                atomicAdd(o + 3, t.w);
            }
            __syncthreads();
            r0 = e; ++s;
        }
    } else {
        // ------------- fine: 32 float4 cols, 4 row lanes ---------------
        const int c  = tid & 31;
        const int rr = tid >> 5;

        int r0 = (blockIdx.x - NT_C) * TILE_F;
        int r1 = r0 + TILE_F; if (r1 > n_f) r1 = n_f;

        int s = 0;
        while (scum[s + 1] <= r0) ++s;

        while (r0 < r1) {
            int e = scum[s + 1]; if (e > r1) e = r1;

            float4 acc = make_float4(0.f, 0.f, 0.f, 0.f);
            const float4* base = feats_f + c;
#pragma unroll 4
            for (int r = r0 + rr; r < e; r += 4) {
                float4 v = __ldcs(base + (size_t)r * 32);
                acc.x += v.x; acc.y += v.y; acc.z += v.z; acc.w += v.w;
            }

            shred[tid] = acc;
            __syncthreads();
            if (rr == 0) {
                float4 v1 = shred[32 + c], v2 = shred[64 + c], v3 = shred[96 + c];
                float4 t  = shred[c];
                t.x += v1.x + v2.x + v3.x;
                t.y += v1.y + v2.y + v3.y;
                t.z += v1.z + v2.z + v3.z;
                t.w += v1.w + v2.w + v3.w;
                float* o = g_scratch + s * D_OUT + D_C + c * 4;
                atomicAdd(o + 0, t.x);
                atomicAdd(o + 1, t.y);
                atomicAdd(o + 2, t.z);
                atomicAdd(o + 3, t.w);
            }
            __syncthreads();
            r0 = e; ++s;
        }
    }

    // ---- last block to finish performs finalize + state reset ----
    if (tid == 0) {
        __threadfence();
        unsigned int old = atomicAdd(&g_count, 1u);
        sdone = (old == gridDim.x - 1);
    }
    __syncthreads();

    if (sdone) {
        __threadfence();  // make all blocks' atomics visible to this block
        for (int i = tid; i < B_SEG * D_OUT; i += 128) {
            int b = i / D_OUT;
            int d = i - b * D_OUT;
            int len = (d < D_C) ? lengths_c[b] : lengths_f[b];
            out[i] = g_scratch[i] / (float)len;
            g_scratch[i] = 0.0f;
        }
        __syncthreads();
        if (tid == 0) g_count = 0u;
    }
}

// ---------------------------------------------------------------------------
extern "C" void kernel_launch(void* const* d_in, const int* in_sizes, int n_in,
                              void* d_out, int out_size) {
    const float* feats_f   = (const float*)d_in[0];   // [524288, 128]
    const float* feats_c   = (const float*)d_in[1];   // [32768, 256]
    const int*   lengths_f = (const int*)d_in[2];     // [16]
    const int*   lengths_c = (const int*)d_in[3];     // [16]
    float* out = (float*)d_out;                       // [16, 384]

    const int n_f = in_sizes[0] / D_F;   // total fine rows
    const int n_c = in_sizes[1] / D_C;   // total coarse rows

    const int nblk = NT_C + (n_f + TILE_F - 1) / TILE_F;   // 4608
    pare_mw_kernel<<<nblk, 128>>>((const float4*)feats_c,
                                  (const float4*)feats_f,
                                  lengths_c, lengths_f, out, n_c, n_f);
}

// round 11
// speedup vs baseline: 1.2876x; 1.2876x over previous
#include <cuda_runtime.h>
#include <cuda_bf16.h>
#include <cstdint>

// Problem constants (fixed by the reference)
#define B_SEG   16
#define D_F     128            // fine feature dim  (32 float4)
#define D_C     256            // coarse feature dim (64 float4)
#define D_OUT   (D_C + D_F)    // 384

// Exactly one full wave on 148 SMs at occupancy 8: 148*8 = 1184 CTAs.
// Byte-balanced split: coarse tile ~248KB, fine tile ~249KB.
#define NT_C    132            // coarse tiles
#define NT_F    1052           // fine tiles
#define NBLK    (NT_C + NT_F)  // 1184

// Self-restoring device state (zero at module load; finalize resets it).
__device__ float        g_scratch[B_SEG * D_OUT];
__device__ unsigned int g_count = 0u;

// ---------------------------------------------------------------------------
// Single fused kernel: segment-sum over both tensors + last-block finalize.
// Fast prologue: every warp loads lengths in parallel (lane<16) and does a
// shfl inclusive scan; all warps write identical values to smem (benign
// race), so only __syncwarp is needed before the streaming loop starts.
// ---------------------------------------------------------------------------
__global__ __launch_bounds__(256, 8)
void pare_fused_kernel(const float4* __restrict__ feats_c,
                       const float4* __restrict__ feats_f,
                       const int* __restrict__ lengths_c,
                       const int* __restrict__ lengths_f,
                       float* __restrict__ out,
                       int n_c, int n_f) {
    __shared__ float4 shred[256];
    __shared__ int    scum[B_SEG + 1];
    __shared__ bool   sdone;
    const int tid  = threadIdx.x;
    const int lane = tid & 31;

    const bool is_c = (blockIdx.x < NT_C);

    // ---- parallel cumsum prologue (~400 cycles, no block barrier) ----
    {
        const int* L = is_c ? lengths_c : lengths_f;
        int v = (lane < B_SEG) ? __ldg(L + lane) : 0;
#pragma unroll
        for (int o = 1; o < B_SEG; o <<= 1) {
            int n = __shfl_up_sync(0xFFFFFFFFu, v, o);
            if (lane >= o) v += n;
        }
        if (lane < B_SEG) scum[lane + 1] = v;   // same values from every warp
        if (lane == 0)    scum[0] = 0;
        __syncwarp();
    }

    if (is_c) {
        // ------------- coarse: 64 float4 cols, 4 row lanes -------------
        const int c  = tid & 63;
        const int rr = tid >> 6;
        const int t  = blockIdx.x;

        int r0 = (int)(((long long)t)       * n_c / NT_C);
        int r1 = (int)(((long long)(t + 1)) * n_c / NT_C);

        int s = 0;
        while (scum[s + 1] <= r0) ++s;

        while (r0 < r1) {
            int e = scum[s + 1]; if (e > r1) e = r1;

            float4 acc = make_float4(0.f, 0.f, 0.f, 0.f);
            const float4* base = feats_c + c;
#pragma unroll 4
            for (int r = r0 + rr; r < e; r += 4) {
                float4 v = __ldcs(base + (size_t)r * 64);
                acc.x += v.x; acc.y += v.y; acc.z += v.z; acc.w += v.w;
            }

            shred[tid] = acc;
            __syncthreads();
            if (rr == 0) {
                float4 v1 = shred[64 + c], v2 = shred[128 + c], v3 = shred[192 + c];
                float4 tt = shred[c];
                tt.x += v1.x + v2.x + v3.x;
                tt.y += v1.y + v2.y + v3.y;
                tt.z += v1.z + v2.z + v3.z;
                tt.w += v1.w + v2.w + v3.w;
                float* o = g_scratch + s * D_OUT + c * 4;
                atomicAdd(o + 0, tt.x);
                atomicAdd(o + 1, tt.y);
                atomicAdd(o + 2, tt.z);
                atomicAdd(o + 3, tt.w);
            }
            __syncthreads();
            r0 = e; ++s;
        }
    } else {
        // ------------- fine: 32 float4 cols, 8 row lanes ---------------
        const int c  = tid & 31;
        const int rr = tid >> 5;
        const int t  = blockIdx.x - NT_C;

        int r0 = (int)(((long long)t)       * n_f / NT_F);
        int r1 = (int)(((long long)(t + 1)) * n_f / NT_F);

        int s = 0;
        while (scum[s + 1] <= r0) ++s;

        while (r0 < r1) {
            int e = scum[s + 1]; if (e > r1) e = r1;

            float4 acc = make_float4(0.f, 0.f, 0.f, 0.f);
            const float4* base = feats_f + c;
#pragma unroll 4
            for (int r = r0 + rr; r < e; r += 8) {
                float4 v = __ldcs(base + (size_t)r * 32);
                acc.x += v.x; acc.y += v.y; acc.z += v.z; acc.w += v.w;
            }

            shred[tid] = acc;
            __syncthreads();
            if (rr == 0) {
                float4 tt = shred[c];
#pragma unroll
                for (int k = 1; k < 8; ++k) {
                    float4 v = shred[k * 32 + c];
                    tt.x += v.x; tt.y += v.y; tt.z += v.z; tt.w += v.w;
                }
                float* o = g_scratch + s * D_OUT + D_C + c * 4;
                atomicAdd(o + 0, tt.x);
                atomicAdd(o + 1, tt.y);
                atomicAdd(o + 2, tt.z);
                atomicAdd(o + 3, tt.w);
            }
            __syncthreads();
            r0 = e; ++s;
        }
    }

    // ---- last block to finish performs finalize + state reset ----
    if (tid == 0) {
        __threadfence();
        unsigned int old = atomicAdd(&g_count, 1u);
        sdone = (old == gridDim.x - 1);
    }
    __syncthreads();

    if (sdone) {
        __threadfence();  // make all blocks' atomics visible to this block
        for (int i = tid; i < B_SEG * D_OUT; i += 256) {
            int b = i / D_OUT;
            int d = i - b * D_OUT;
            int len = (d < D_C) ? lengths_c[b] : lengths_f[b];
            out[i] = g_scratch[i] / (float)len;
            g_scratch[i] = 0.0f;
        }
        __syncthreads();
        if (tid == 0) g_count = 0u;
    }
}

// ---------------------------------------------------------------------------
extern "C" void kernel_launch(void* const* d_in, const int* in_sizes, int n_in,
                              void* d_out, int out_size) {
    const float* feats_f   = (const float*)d_in[0];   // [524288, 128]
    const float* feats_c   = (const float*)d_in[1];   // [32768, 256]
    const int*   lengths_f = (const int*)d_in[2];     // [16]
    const int*   lengths_c = (const int*)d_in[3];     // [16]
    float* out = (float*)d_out;                       // [16, 384]

    const int n_f = in_sizes[0] / D_F;   // total fine rows
    const int n_c = in_sizes[1] / D_C;   // total coarse rows

    pare_fused_kernel<<<NBLK, 256>>>((const float4*)feats_c,
                                     (const float4*)feats_f,
                                     lengths_c, lengths_f, out, n_c, n_f);
}